// round 12
// baseline (speedup 1.0000x reference)
#include <cuda_runtime.h>
#include <cuda_bf16.h>
#include <cuda_fp16.h>
#include <cstdint>

#define NN     100000
#define EE     1600000
#define IN_F   256
#define HID_F  128
#define OUT_F  64

// ---------------- scratch (device globals; no runtime allocation) -----------
__device__ int   g_deg_out[NN];
__device__ int   g_deg_in [NN];
__device__ float g_dout_inv[NN];
__device__ float g_din_inv [NN];
__device__ int   g_offs  [NN];
__device__ int   g_cursor[NN];
__device__ int   g_bsums [128];
__device__ int   g_csr_src[EE];
__device__ __align__(16) __half g_Y1h[(size_t)NN * HID_F];       // layer1 GEMM out (fp16)
__device__ __align__(16) uint16_t g_X2h[(size_t)NN * HID_F];     // X2 hi (bf16)
__device__ __align__(16) uint16_t g_X2l[(size_t)NN * HID_F];     // X2 lo (bf16)
__device__ __align__(16) __half g_Y2h[(size_t)NN * OUT_F];       // layer2 GEMM out (fp16)
__device__ __align__(16) uint16_t g_W1Th[HID_F * IN_F];          // W1^T hi  [n][k]
__device__ __align__(16) uint16_t g_W1Tl[HID_F * IN_F];          // W1^T lo
__device__ __align__(16) uint16_t g_W2Th[OUT_F * HID_F];         // W2^T hi  [n][k]
__device__ __align__(16) uint16_t g_W2Tl[OUT_F * HID_F];         // W2^T lo

// ---------------- helpers ---------------------------------------------------
__device__ __forceinline__ int warp_incl_scan(int x) {
#pragma unroll
    for (int d = 1; d < 32; d <<= 1) {
        int y = __shfl_up_sync(0xffffffffu, x, d);
        if ((threadIdx.x & 31) >= d) x += y;
    }
    return x;
}

// split fp32 pair -> packed bf16 hi / lo (x in low 16 bits)
__device__ __forceinline__ void split2(float x, float y, uint32_t& h, uint32_t& l) {
    __nv_bfloat16 hx = __float2bfloat16(x);
    __nv_bfloat16 hy = __float2bfloat16(y);
    __nv_bfloat16 lx = __float2bfloat16(x - __bfloat162float(hx));
    __nv_bfloat16 ly = __float2bfloat16(y - __bfloat162float(hy));
    h = (uint32_t)__bfloat16_as_ushort(hx) | ((uint32_t)__bfloat16_as_ushort(hy) << 16);
    l = (uint32_t)__bfloat16_as_ushort(lx) | ((uint32_t)__bfloat16_as_ushort(ly) << 16);
}

__device__ __forceinline__ void mma_bf16(float* c, const uint32_t* a, const uint32_t* b) {
    asm volatile(
        "mma.sync.aligned.m16n8k16.row.col.f32.bf16.bf16.f32 "
        "{%0,%1,%2,%3}, {%4,%5,%6,%7}, {%8,%9}, {%0,%1,%2,%3};\n"
        : "+f"(c[0]), "+f"(c[1]), "+f"(c[2]), "+f"(c[3])
        : "r"(a[0]), "r"(a[1]), "r"(a[2]), "r"(a[3]), "r"(b[0]), "r"(b[1]));
}

// accumulate 8 fp16 (one uint4) into 8 fp32 accumulators
__device__ __forceinline__ void acc8(float* a, uint4 v) {
    __half2* p = reinterpret_cast<__half2*>(&v);
#pragma unroll
    for (int i = 0; i < 4; i++) {
        float2 f = __half22float2(p[i]);
        a[2 * i]     += f.x;
        a[2 * i + 1] += f.y;
    }
}

// ---------------- degrees / scan / CSR --------------------------------------
__global__ void zero_degs() {
    int i = blockIdx.x * blockDim.x + threadIdx.x;
    if (i < NN) { g_deg_out[i] = 0; g_deg_in[i] = 0; }
}

__global__ void hist_kernel(const int* __restrict__ src, const int* __restrict__ dst) {
    int e = blockIdx.x * blockDim.x + threadIdx.x;
    if (e < EE) {
        atomicAdd(&g_deg_out[src[e]], 1);
        atomicAdd(&g_deg_in [dst[e]], 1);
    }
}

__global__ void scan_block_k() {
    __shared__ int wsum[32];
    int i = blockIdx.x * 1024 + threadIdx.x;
    int v = (i < NN) ? g_deg_in[i] : 0;
    int x = warp_incl_scan(v);
    if ((threadIdx.x & 31) == 31) wsum[threadIdx.x >> 5] = x;
    __syncthreads();
    if (threadIdx.x < 32) {
        int w  = wsum[threadIdx.x];
        int wx = warp_incl_scan(w);
        wsum[threadIdx.x] = wx - w;
        if (threadIdx.x == 31) g_bsums[blockIdx.x] = wx;
    }
    __syncthreads();
    int excl = x - v + wsum[threadIdx.x >> 5];
    if (i < NN) g_offs[i] = excl;
}

__global__ void scan_top_k(int nb) {
    __shared__ int wsum[4];
    int t = threadIdx.x;
    int v = (t < nb) ? g_bsums[t] : 0;
    int x = warp_incl_scan(v);
    if ((t & 31) == 31) wsum[t >> 5] = x;
    __syncthreads();
    if (t == 0) {
        int run = 0;
#pragma unroll
        for (int w = 0; w < 4; w++) { int tmp = wsum[w]; wsum[w] = run; run += tmp; }
    }
    __syncthreads();
    int excl = x - v + wsum[t >> 5];
    if (t < nb) g_bsums[t] = excl;
}

// fused: finalize offsets/cursors AND compute degree normalizers
__global__ void scan_add_k() {
    int i = blockIdx.x * 1024 + threadIdx.x;
    if (i < NN) {
        int o = g_offs[i] + g_bsums[blockIdx.x];
        g_offs[i]   = o;
        g_cursor[i] = o;
        g_dout_inv[i] = rsqrtf(fmaxf((float)g_deg_out[i], 1.0f));
        g_din_inv[i]  = rsqrtf(fmaxf((float)g_deg_in[i],  1.0f));
    }
}

__global__ void csr_fill(const int* __restrict__ src, const int* __restrict__ dst) {
    int e = blockIdx.x * blockDim.x + threadIdx.x;
    if (e < EE) {
        int pos = atomicAdd(&g_cursor[dst[e]], 1);
        g_csr_src[pos] = src[e];
    }
}

// ---------------- weight split/transpose (merged) ----------------------------
__global__ void split_weights(const float* __restrict__ W1, const float* __restrict__ W2) {
    int idx = blockIdx.x * blockDim.x + threadIdx.x;
    if (idx < IN_F * HID_F) {
        int k = idx / HID_F, n = idx % HID_F;
        float v = W1[idx];
        __nv_bfloat16 h = __float2bfloat16(v);
        __nv_bfloat16 l = __float2bfloat16(v - __bfloat162float(h));
        g_W1Th[n * IN_F + k] = __bfloat16_as_ushort(h);
        g_W1Tl[n * IN_F + k] = __bfloat16_as_ushort(l);
    } else if (idx < IN_F * HID_F + HID_F * OUT_F) {
        int i2 = idx - IN_F * HID_F;
        int k = i2 / OUT_F, n = i2 % OUT_F;
        float v = W2[i2];
        __nv_bfloat16 h = __float2bfloat16(v);
        __nv_bfloat16 l = __float2bfloat16(v - __bfloat162float(h));
        g_W2Th[n * HID_F + k] = __bfloat16_as_ushort(h);
        g_W2Tl[n * HID_F + k] = __bfloat16_as_ushort(l);
    }
}

// ---------------- GEMM1: Y1 = (X * dout) @ W1, split-bf16 tensor cores ------
#define AST 40
__global__ void __launch_bounds__(256) gemm1_k(const float* __restrict__ A) {
    __shared__ uint16_t As_h[64 * AST],  As_l[64 * AST];
    __shared__ uint16_t Bs_h[128 * AST], Bs_l[128 * AST];

    const int tid  = threadIdx.x;
    const int lane = tid & 31;
    const int wid  = tid >> 5;
    const int wm   = wid >> 2;
    const int wn   = wid & 3;
    const int g    = lane >> 2;
    const int tq   = lane & 3;
    const int m0   = blockIdx.x * 64;

    float acc[2][4][4];
#pragma unroll
    for (int mi = 0; mi < 2; mi++)
#pragma unroll
        for (int ni = 0; ni < 4; ni++)
#pragma unroll
            for (int r = 0; r < 4; r++) acc[mi][ni][r] = 0.f;

    for (int kt = 0; kt < IN_F; kt += 32) {
#pragma unroll
        for (int i = 0; i < 2; i++) {
            int idx = tid + i * 256;
            int r = idx >> 3, c = idx & 7;
            int grow = m0 + r;
            float4 v = make_float4(0.f, 0.f, 0.f, 0.f);
            if (grow < NN) {
                v = *reinterpret_cast<const float4*>(&A[(size_t)grow * IN_F + kt + c * 4]);
                float s = g_dout_inv[grow];
                v.x *= s; v.y *= s; v.z *= s; v.w *= s;
            }
            uint32_t h01, l01, h23, l23;
            split2(v.x, v.y, h01, l01);
            split2(v.z, v.w, h23, l23);
            *reinterpret_cast<uint32_t*>(&As_h[r * AST + c * 4])     = h01;
            *reinterpret_cast<uint32_t*>(&As_h[r * AST + c * 4 + 2]) = h23;
            *reinterpret_cast<uint32_t*>(&As_l[r * AST + c * 4])     = l01;
            *reinterpret_cast<uint32_t*>(&As_l[r * AST + c * 4 + 2]) = l23;
        }
#pragma unroll
        for (int i = 0; i < 2; i++) {
            int idx = tid + i * 256;
            int n = idx >> 2, c = idx & 3;
            *reinterpret_cast<uint4*>(&Bs_h[n * AST + c * 8]) =
                *reinterpret_cast<const uint4*>(&g_W1Th[n * IN_F + kt + c * 8]);
            *reinterpret_cast<uint4*>(&Bs_l[n * AST + c * 8]) =
                *reinterpret_cast<const uint4*>(&g_W1Tl[n * IN_F + kt + c * 8]);
        }
        __syncthreads();

#pragma unroll
        for (int ks = 0; ks < 2; ks++) {
            uint32_t ah[2][4], al[2][4], bh[4][2], bl[4][2];
#pragma unroll
            for (int mi = 0; mi < 2; mi++) {
                const uint16_t* pH = &As_h[(wm * 32 + mi * 16 + g) * AST + ks * 16 + tq * 2];
                const uint16_t* pL = &As_l[(wm * 32 + mi * 16 + g) * AST + ks * 16 + tq * 2];
                ah[mi][0] = *reinterpret_cast<const uint32_t*>(pH);
                ah[mi][1] = *reinterpret_cast<const uint32_t*>(pH + 8 * AST);
                ah[mi][2] = *reinterpret_cast<const uint32_t*>(pH + 8);
                ah[mi][3] = *reinterpret_cast<const uint32_t*>(pH + 8 * AST + 8);
                al[mi][0] = *reinterpret_cast<const uint32_t*>(pL);
                al[mi][1] = *reinterpret_cast<const uint32_t*>(pL + 8 * AST);
                al[mi][2] = *reinterpret_cast<const uint32_t*>(pL + 8);
                al[mi][3] = *reinterpret_cast<const uint32_t*>(pL + 8 * AST + 8);
            }
#pragma unroll
            for (int ni = 0; ni < 4; ni++) {
                const uint16_t* pH = &Bs_h[(wn * 32 + ni * 8 + g) * AST + ks * 16 + tq * 2];
                const uint16_t* pL = &Bs_l[(wn * 32 + ni * 8 + g) * AST + ks * 16 + tq * 2];
                bh[ni][0] = *reinterpret_cast<const uint32_t*>(pH);
                bh[ni][1] = *reinterpret_cast<const uint32_t*>(pH + 8);
                bl[ni][0] = *reinterpret_cast<const uint32_t*>(pL);
                bl[ni][1] = *reinterpret_cast<const uint32_t*>(pL + 8);
            }
#pragma unroll
            for (int mi = 0; mi < 2; mi++)
#pragma unroll
                for (int ni = 0; ni < 4; ni++) {
                    mma_bf16(acc[mi][ni], ah[mi], bh[ni]);
                    mma_bf16(acc[mi][ni], ah[mi], bl[ni]);
                    mma_bf16(acc[mi][ni], al[mi], bh[ni]);
                }
        }
        __syncthreads();
    }

#pragma unroll
    for (int mi = 0; mi < 2; mi++)
#pragma unroll
        for (int ni = 0; ni < 4; ni++) {
            int row0 = m0 + wm * 32 + mi * 16 + g;
            int col  = wn * 32 + ni * 8 + tq * 2;
            if (row0 < NN)
                *reinterpret_cast<__half2*>(&g_Y1h[(size_t)row0 * HID_F + col]) =
                    __floats2half2_rn(acc[mi][ni][0], acc[mi][ni][1]);
            if (row0 + 8 < NN)
                *reinterpret_cast<__half2*>(&g_Y1h[(size_t)(row0 + 8) * HID_F + col]) =
                    __floats2half2_rn(acc[mi][ni][2], acc[mi][ni][3]);
        }
}

// ---------------- GEMM2: Y2 = X2 @ W2 (fp16 out) -----------------------------
__global__ void __launch_bounds__(256) gemm2_k() {
    __shared__ uint16_t As_h[64 * AST], As_l[64 * AST];
    __shared__ uint16_t Bs_h[64 * AST], Bs_l[64 * AST];

    const int tid  = threadIdx.x;
    const int lane = tid & 31;
    const int wid  = tid >> 5;
    const int wm   = wid >> 2;
    const int wn   = wid & 3;
    const int g    = lane >> 2;
    const int tq   = lane & 3;
    const int m0   = blockIdx.x * 64;

    float acc[2][2][4];
#pragma unroll
    for (int mi = 0; mi < 2; mi++)
#pragma unroll
        for (int ni = 0; ni < 2; ni++)
#pragma unroll
            for (int r = 0; r < 4; r++) acc[mi][ni][r] = 0.f;

    for (int kt = 0; kt < HID_F; kt += 32) {
        {
            int r = tid >> 2, c = tid & 3;
            int grow = m0 + r;
            uint4 vh = make_uint4(0u, 0u, 0u, 0u), vl = vh;
            if (grow < NN) {
                vh = *reinterpret_cast<const uint4*>(&g_X2h[(size_t)grow * HID_F + kt + c * 8]);
                vl = *reinterpret_cast<const uint4*>(&g_X2l[(size_t)grow * HID_F + kt + c * 8]);
            }
            *reinterpret_cast<uint4*>(&As_h[r * AST + c * 8]) = vh;
            *reinterpret_cast<uint4*>(&As_l[r * AST + c * 8]) = vl;
        }
        {
            int n = tid >> 2, c = tid & 3;
            *reinterpret_cast<uint4*>(&Bs_h[n * AST + c * 8]) =
                *reinterpret_cast<const uint4*>(&g_W2Th[n * HID_F + kt + c * 8]);
            *reinterpret_cast<uint4*>(&Bs_l[n * AST + c * 8]) =
                *reinterpret_cast<const uint4*>(&g_W2Tl[n * HID_F + kt + c * 8]);
        }
        __syncthreads();

#pragma unroll
        for (int ks = 0; ks < 2; ks++) {
            uint32_t ah[2][4], al[2][4], bh[2][2], bl[2][2];
#pragma unroll
            for (int mi = 0; mi < 2; mi++) {
                const uint16_t* pH = &As_h[(wm * 32 + mi * 16 + g) * AST + ks * 16 + tq * 2];
                const uint16_t* pL = &As_l[(wm * 32 + mi * 16 + g) * AST + ks * 16 + tq * 2];
                ah[mi][0] = *reinterpret_cast<const uint32_t*>(pH);
                ah[mi][1] = *reinterpret_cast<const uint32_t*>(pH + 8 * AST);
                ah[mi][2] = *reinterpret_cast<const uint32_t*>(pH + 8);
                ah[mi][3] = *reinterpret_cast<const uint32_t*>(pH + 8 * AST + 8);
                al[mi][0] = *reinterpret_cast<const uint32_t*>(pL);
                al[mi][1] = *reinterpret_cast<const uint32_t*>(pL + 8 * AST);
                al[mi][2] = *reinterpret_cast<const uint32_t*>(pL + 8);
                al[mi][3] = *reinterpret_cast<const uint32_t*>(pL + 8 * AST + 8);
            }
#pragma unroll
            for (int ni = 0; ni < 2; ni++) {
                const uint16_t* pH = &Bs_h[(wn * 16 + ni * 8 + g) * AST + ks * 16 + tq * 2];
                const uint16_t* pL = &Bs_l[(wn * 16 + ni * 8 + g) * AST + ks * 16 + tq * 2];
                bh[ni][0] = *reinterpret_cast<const uint32_t*>(pH);
                bh[ni][1] = *reinterpret_cast<const uint32_t*>(pH + 8);
                bl[ni][0] = *reinterpret_cast<const uint32_t*>(pL);
                bl[ni][1] = *reinterpret_cast<const uint32_t*>(pL + 8);
            }
#pragma unroll
            for (int mi = 0; mi < 2; mi++)
#pragma unroll
                for (int ni = 0; ni < 2; ni++) {
                    mma_bf16(acc[mi][ni], ah[mi], bh[ni]);
                    mma_bf16(acc[mi][ni], ah[mi], bl[ni]);
                    mma_bf16(acc[mi][ni], al[mi], bh[ni]);
                }
        }
        __syncthreads();
    }

#pragma unroll
    for (int mi = 0; mi < 2; mi++)
#pragma unroll
        for (int ni = 0; ni < 2; ni++) {
            int row0 = m0 + wm * 32 + mi * 16 + g;
            int col  = wn * 16 + ni * 8 + tq * 2;
            if (row0 < NN)
                *reinterpret_cast<__half2*>(&g_Y2h[(size_t)row0 * OUT_F + col]) =
                    __floats2half2_rn(acc[mi][ni][0], acc[mi][ni][1]);
            if (row0 + 8 < NN)
                *reinterpret_cast<__half2*>(&g_Y2h[(size_t)(row0 + 8) * OUT_F + col]) =
                    __floats2half2_rn(acc[mi][ni][2], acc[mi][ni][3]);
        }
}

// ---------------- CSR gather, layer 1 ----------------------------------------
// warp per node; two half-warps process even/odd edges; lane owns 8 feats (uint4).
__global__ void __launch_bounds__(256) gather1(const float* __restrict__ b1) {
    const unsigned FULL = 0xffffffffu;
    int node = blockIdx.x * 8 + (threadIdx.x >> 5);
    if (node >= NN) return;
    int lane = threadIdx.x & 31;
    int half = lane >> 4;                  // 0/1: even/odd edges
    int hl   = lane & 15;                  // feats [hl*8, hl*8+8)
    int start = g_offs[node];
    int cnt   = g_deg_in[node];

    float a[8];
#pragma unroll
    for (int k = 0; k < 8; k++) a[k] = 0.f;

    for (int j0 = 0; j0 < cnt; j0 += 32) {
        int m  = min(32, cnt - j0);
        int id = (lane < m) ? __ldg(&g_csr_src[start + j0 + lane]) : 0;
        int nt   = (m + 1) >> 1;           // per-half iterations (uniform)
        int safe = m >> 1;                 // fully-valid iterations
        int j = 0;
        for (; j + 4 <= safe; j += 4) {
            int e0 = 2 * j + half;
            int s0 = __shfl_sync(FULL, id, e0);
            int s1 = __shfl_sync(FULL, id, e0 + 2);
            int s2 = __shfl_sync(FULL, id, e0 + 4);
            int s3 = __shfl_sync(FULL, id, e0 + 6);
            uint4 v0 = *reinterpret_cast<const uint4*>(&g_Y1h[(size_t)s0 * HID_F + hl * 8]);
            uint4 v1 = *reinterpret_cast<const uint4*>(&g_Y1h[(size_t)s1 * HID_F + hl * 8]);
            uint4 v2 = *reinterpret_cast<const uint4*>(&g_Y1h[(size_t)s2 * HID_F + hl * 8]);
            uint4 v3 = *reinterpret_cast<const uint4*>(&g_Y1h[(size_t)s3 * HID_F + hl * 8]);
            acc8(a, v0); acc8(a, v1); acc8(a, v2); acc8(a, v3);
        }
        for (; j < nt; j++) {
            int e = 2 * j + half;
            int s = __shfl_sync(FULL, id, e < m ? e : 0);
            if (e < m) {
                uint4 v = *reinterpret_cast<const uint4*>(&g_Y1h[(size_t)s * HID_F + hl * 8]);
                acc8(a, v);
            }
        }
    }

    // combine halves
#pragma unroll
    for (int k = 0; k < 8; k++) a[k] += __shfl_xor_sync(FULL, a[k], 16);

    if (half == 0) {
        float di = g_din_inv[node], dd = g_dout_inv[node];
        float4 b0 = *reinterpret_cast<const float4*>(&b1[hl * 8]);
        float4 b1v = *reinterpret_cast<const float4*>(&b1[hl * 8 + 4]);
        float f[8];
        f[0] = fmaxf(a[0] * di + b0.x, 0.f) * dd;
        f[1] = fmaxf(a[1] * di + b0.y, 0.f) * dd;
        f[2] = fmaxf(a[2] * di + b0.z, 0.f) * dd;
        f[3] = fmaxf(a[3] * di + b0.w, 0.f) * dd;
        f[4] = fmaxf(a[4] * di + b1v.x, 0.f) * dd;
        f[5] = fmaxf(a[5] * di + b1v.y, 0.f) * dd;
        f[6] = fmaxf(a[6] * di + b1v.z, 0.f) * dd;
        f[7] = fmaxf(a[7] * di + b1v.w, 0.f) * dd;
        uint32_t h0, l0, h1, l1, h2, l2, h3, l3;
        split2(f[0], f[1], h0, l0);
        split2(f[2], f[3], h1, l1);
        split2(f[4], f[5], h2, l2);
        split2(f[6], f[7], h3, l3);
        size_t o = (size_t)node * HID_F + hl * 8;
        *reinterpret_cast<uint4*>(&g_X2h[o]) = make_uint4(h0, h1, h2, h3);
        *reinterpret_cast<uint4*>(&g_X2l[o]) = make_uint4(l0, l1, l2, l3);
    }
}

// ---------------- CSR gather, layer 2 ----------------------------------------
// warp per node; four quarter-warps process edges mod 4; lane owns 8 feats (uint4 fp16).
__global__ void __launch_bounds__(256) gather2(float* __restrict__ out,
                                               const float* __restrict__ b2) {
    const unsigned FULL = 0xffffffffu;
    int node = blockIdx.x * 8 + (threadIdx.x >> 5);
    if (node >= NN) return;
    int lane = threadIdx.x & 31;
    int q  = lane >> 3;                    // 0..3: edges mod 4
    int ql = lane & 7;                     // feats [ql*8, ql*8+8)
    int start = g_offs[node];
    int cnt   = g_deg_in[node];

    float a[8];
#pragma unroll
    for (int k = 0; k < 8; k++) a[k] = 0.f;

    for (int j0 = 0; j0 < cnt; j0 += 32) {
        int m  = min(32, cnt - j0);
        int id = (lane < m) ? __ldg(&g_csr_src[start + j0 + lane]) : 0;
        int nt   = (m + 3) >> 2;
        int safe = m >> 2;
        int j = 0;
        for (; j + 2 <= safe; j += 2) {
            int e0 = 4 * j + q;
            int s0 = __shfl_sync(FULL, id, e0);
            int s1 = __shfl_sync(FULL, id, e0 + 4);
            uint4 v0 = *reinterpret_cast<const uint4*>(&g_Y2h[(size_t)s0 * OUT_F + ql * 8]);
            uint4 v1 = *reinterpret_cast<const uint4*>(&g_Y2h[(size_t)s1 * OUT_F + ql * 8]);
            acc8(a, v0); acc8(a, v1);
        }
        for (; j < nt; j++) {
            int e = 4 * j + q;
            int s = __shfl_sync(FULL, id, e < m ? e : 0);
            if (e < m) {
                uint4 v = *reinterpret_cast<const uint4*>(&g_Y2h[(size_t)s * OUT_F + ql * 8]);
                acc8(a, v);
            }
        }
    }

    // combine quarters
#pragma unroll
    for (int k = 0; k < 8; k++) {
        a[k] += __shfl_xor_sync(FULL, a[k], 8);
        a[k] += __shfl_xor_sync(FULL, a[k], 16);
    }

    if (q == 0) {
        float di = g_din_inv[node];
        float4 b0 = *reinterpret_cast<const float4*>(&b2[ql * 8]);
        float4 b1v = *reinterpret_cast<const float4*>(&b2[ql * 8 + 4]);
        float4 o0, o1;
        o0.x = a[0] * di + b0.x;  o0.y = a[1] * di + b0.y;
        o0.z = a[2] * di + b0.z;  o0.w = a[3] * di + b0.w;
        o1.x = a[4] * di + b1v.x; o1.y = a[5] * di + b1v.y;
        o1.z = a[6] * di + b1v.z; o1.w = a[7] * di + b1v.w;
        size_t o = (size_t)node * OUT_F + ql * 8;
        *reinterpret_cast<float4*>(&out[o])     = o0;
        *reinterpret_cast<float4*>(&out[o + 4]) = o1;
    }
}

// ---------------- launch ----------------------------------------------------
extern "C" void kernel_launch(void* const* d_in, const int* in_sizes, int n_in,
                              void* d_out, int out_size) {
    (void)in_sizes; (void)n_in; (void)out_size;
    const float* features = (const float*)d_in[0];
    const int*   src      = (const int*)  d_in[1];
    const int*   dst      = (const int*)  d_in[2];
    const float* W1       = (const float*)d_in[3];
    const float* b1       = (const float*)d_in[4];
    const float* W2       = (const float*)d_in[5];
    const float* b2       = (const float*)d_in[6];
    float*       out      = (float*)      d_out;

    const int TPB = 256;
    const int SCAN_BLOCKS = (NN + 1023) / 1024;
    const int WTOT = IN_F * HID_F + HID_F * OUT_F;

    // degrees + CSR build + weight prep
    zero_degs<<<(NN + TPB - 1) / TPB, TPB>>>();
    hist_kernel<<<(EE + TPB - 1) / TPB, TPB>>>(src, dst);
    scan_block_k<<<SCAN_BLOCKS, 1024>>>();
    scan_top_k<<<1, 128>>>(SCAN_BLOCKS);
    scan_add_k<<<SCAN_BLOCKS, 1024>>>();
    csr_fill<<<(EE + TPB - 1) / TPB, TPB>>>(src, dst);
    split_weights<<<(WTOT + TPB - 1) / TPB, TPB>>>(W1, W2);

    // layer 1
    gemm1_k<<<(NN + 63) / 64, 256>>>(features);
    gather1<<<(NN + 7) / 8, TPB>>>(b1);

    // layer 2
    gemm2_k<<<(NN + 63) / 64, 256>>>();
    gather2<<<(NN + 7) / 8, TPB>>>(out, b2);
}

// round 13
// speedup vs baseline: 1.1136x; 1.1136x over previous
#include <cuda_runtime.h>
#include <cuda_bf16.h>
#include <cuda_fp16.h>
#include <cstdint>

#define NN     100000
#define EE     1600000
#define IN_F   256
#define HID_F  128
#define OUT_F  64

// ---------------- scratch (device globals; no runtime allocation) -----------
__device__ int   g_deg_out[NN];
__device__ int   g_deg_in [NN];
__device__ float g_dout_inv[NN];
__device__ float g_din_inv [NN];
__device__ int   g_offs  [NN];
__device__ int   g_cursor[NN];
__device__ int   g_bsums [128];
__device__ int   g_csr_src[EE];
__device__ __align__(16) __half g_Y1h[(size_t)NN * HID_F];       // X @ W1 (fp16, UNSCALED)
__device__ __align__(16) uint16_t g_X2h[(size_t)NN * HID_F];     // X2 hi (bf16)
__device__ __align__(16) uint16_t g_X2l[(size_t)NN * HID_F];     // X2 lo (bf16)
__device__ __align__(16) __half g_Y2h[(size_t)NN * OUT_F];       // X2 @ W2 (fp16)
__device__ __align__(16) uint16_t g_W1Th[HID_F * IN_F];          // W1^T hi  [n][k]
__device__ __align__(16) uint16_t g_W1Tl[HID_F * IN_F];          // W1^T lo
__device__ __align__(16) uint16_t g_W2Th[OUT_F * HID_F];         // W2^T hi  [n][k]
__device__ __align__(16) uint16_t g_W2Tl[OUT_F * HID_F];         // W2^T lo

// ---------------- side stream for CSR-build overlap (static init: host objs) -
struct SideStream {
    cudaStream_t s;
    cudaEvent_t  ef, ej;
    SideStream() {
        cudaStreamCreateWithFlags(&s, cudaStreamNonBlocking);
        cudaEventCreateWithFlags(&ef, cudaEventDisableTiming);
        cudaEventCreateWithFlags(&ej, cudaEventDisableTiming);
    }
};
static SideStream g_ss;

// ---------------- helpers ---------------------------------------------------
__device__ __forceinline__ int warp_incl_scan(int x) {
#pragma unroll
    for (int d = 1; d < 32; d <<= 1) {
        int y = __shfl_up_sync(0xffffffffu, x, d);
        if ((threadIdx.x & 31) >= d) x += y;
    }
    return x;
}

__device__ __forceinline__ void split2(float x, float y, uint32_t& h, uint32_t& l) {
    __nv_bfloat16 hx = __float2bfloat16(x);
    __nv_bfloat16 hy = __float2bfloat16(y);
    __nv_bfloat16 lx = __float2bfloat16(x - __bfloat162float(hx));
    __nv_bfloat16 ly = __float2bfloat16(y - __bfloat162float(hy));
    h = (uint32_t)__bfloat16_as_ushort(hx) | ((uint32_t)__bfloat16_as_ushort(hy) << 16);
    l = (uint32_t)__bfloat16_as_ushort(lx) | ((uint32_t)__bfloat16_as_ushort(ly) << 16);
}

__device__ __forceinline__ void mma_bf16(float* c, const uint32_t* a, const uint32_t* b) {
    asm volatile(
        "mma.sync.aligned.m16n8k16.row.col.f32.bf16.bf16.f32 "
        "{%0,%1,%2,%3}, {%4,%5,%6,%7}, {%8,%9}, {%0,%1,%2,%3};\n"
        : "+f"(c[0]), "+f"(c[1]), "+f"(c[2]), "+f"(c[3])
        : "r"(a[0]), "r"(a[1]), "r"(a[2]), "r"(a[3]), "r"(b[0]), "r"(b[1]));
}

// acc += scale * (4 fp16 from 8-byte load)
__device__ __forceinline__ void acc_h4s(float4& acc, const __half* p, float s) {
    uint2 u = *reinterpret_cast<const uint2*>(p);
    __half2 ha = *reinterpret_cast<const __half2*>(&u.x);
    __half2 hb = *reinterpret_cast<const __half2*>(&u.y);
    float2 fa = __half22float2(ha);
    float2 fb = __half22float2(hb);
    acc.x = fmaf(s, fa.x, acc.x); acc.y = fmaf(s, fa.y, acc.y);
    acc.z = fmaf(s, fb.x, acc.z); acc.w = fmaf(s, fb.y, acc.w);
}

// ---------------- degrees / scan / CSR --------------------------------------
__global__ void zero_degs() {
    int i = blockIdx.x * blockDim.x + threadIdx.x;
    if (i < NN) { g_deg_out[i] = 0; g_deg_in[i] = 0; }
}

__global__ void hist_kernel(const int* __restrict__ src, const int* __restrict__ dst) {
    int e = blockIdx.x * blockDim.x + threadIdx.x;
    if (e < EE) {
        atomicAdd(&g_deg_out[src[e]], 1);
        atomicAdd(&g_deg_in [dst[e]], 1);
    }
}

__global__ void scan_block_k() {
    __shared__ int wsum[32];
    int i = blockIdx.x * 1024 + threadIdx.x;
    int v = (i < NN) ? g_deg_in[i] : 0;
    int x = warp_incl_scan(v);
    if ((threadIdx.x & 31) == 31) wsum[threadIdx.x >> 5] = x;
    __syncthreads();
    if (threadIdx.x < 32) {
        int w  = wsum[threadIdx.x];
        int wx = warp_incl_scan(w);
        wsum[threadIdx.x] = wx - w;
        if (threadIdx.x == 31) g_bsums[blockIdx.x] = wx;
    }
    __syncthreads();
    int excl = x - v + wsum[threadIdx.x >> 5];
    if (i < NN) g_offs[i] = excl;
}

__global__ void scan_top_k(int nb) {
    __shared__ int wsum[4];
    int t = threadIdx.x;
    int v = (t < nb) ? g_bsums[t] : 0;
    int x = warp_incl_scan(v);
    if ((t & 31) == 31) wsum[t >> 5] = x;
    __syncthreads();
    if (t == 0) {
        int run = 0;
#pragma unroll
        for (int w = 0; w < 4; w++) { int tmp = wsum[w]; wsum[w] = run; run += tmp; }
    }
    __syncthreads();
    int excl = x - v + wsum[t >> 5];
    if (t < nb) g_bsums[t] = excl;
}

// fused: finalize offsets/cursors AND compute degree normalizers
__global__ void scan_add_k() {
    int i = blockIdx.x * 1024 + threadIdx.x;
    if (i < NN) {
        int o = g_offs[i] + g_bsums[blockIdx.x];
        g_offs[i]   = o;
        g_cursor[i] = o;
        g_dout_inv[i] = rsqrtf(fmaxf((float)g_deg_out[i], 1.0f));
        g_din_inv[i]  = rsqrtf(fmaxf((float)g_deg_in[i],  1.0f));
    }
}

__global__ void csr_fill(const int* __restrict__ src, const int* __restrict__ dst) {
    int e = blockIdx.x * blockDim.x + threadIdx.x;
    if (e < EE) {
        int pos = atomicAdd(&g_cursor[dst[e]], 1);
        g_csr_src[pos] = src[e];
    }
}

// ---------------- weight split/transpose (merged) ----------------------------
__global__ void split_weights(const float* __restrict__ W1, const float* __restrict__ W2) {
    int idx = blockIdx.x * blockDim.x + threadIdx.x;
    if (idx < IN_F * HID_F) {
        int k = idx / HID_F, n = idx % HID_F;
        float v = W1[idx];
        __nv_bfloat16 h = __float2bfloat16(v);
        __nv_bfloat16 l = __float2bfloat16(v - __bfloat162float(h));
        g_W1Th[n * IN_F + k] = __bfloat16_as_ushort(h);
        g_W1Tl[n * IN_F + k] = __bfloat16_as_ushort(l);
    } else if (idx < IN_F * HID_F + HID_F * OUT_F) {
        int i2 = idx - IN_F * HID_F;
        int k = i2 / OUT_F, n = i2 % OUT_F;
        float v = W2[i2];
        __nv_bfloat16 h = __float2bfloat16(v);
        __nv_bfloat16 l = __float2bfloat16(v - __bfloat162float(h));
        g_W2Th[n * HID_F + k] = __bfloat16_as_ushort(h);
        g_W2Tl[n * HID_F + k] = __bfloat16_as_ushort(l);
    }
}

// ---------------- GEMM1: Y1 = X @ W1 (UNSCALED), split-bf16 tensor cores ----
#define AST 40
__global__ void __launch_bounds__(256) gemm1_k(const float* __restrict__ A) {
    __shared__ uint16_t As_h[64 * AST],  As_l[64 * AST];
    __shared__ uint16_t Bs_h[128 * AST], Bs_l[128 * AST];

    const int tid  = threadIdx.x;
    const int lane = tid & 31;
    const int wid  = tid >> 5;
    const int wm   = wid >> 2;
    const int wn   = wid & 3;
    const int g    = lane >> 2;
    const int tq   = lane & 3;
    const int m0   = blockIdx.x * 64;

    float acc[2][4][4];
#pragma unroll
    for (int mi = 0; mi < 2; mi++)
#pragma unroll
        for (int ni = 0; ni < 4; ni++)
#pragma unroll
            for (int r = 0; r < 4; r++) acc[mi][ni][r] = 0.f;

    for (int kt = 0; kt < IN_F; kt += 32) {
#pragma unroll
        for (int i = 0; i < 2; i++) {
            int idx = tid + i * 256;
            int r = idx >> 3, c = idx & 7;
            int grow = m0 + r;
            float4 v = make_float4(0.f, 0.f, 0.f, 0.f);
            if (grow < NN)
                v = *reinterpret_cast<const float4*>(&A[(size_t)grow * IN_F + kt + c * 4]);
            uint32_t h01, l01, h23, l23;
            split2(v.x, v.y, h01, l01);
            split2(v.z, v.w, h23, l23);
            *reinterpret_cast<uint32_t*>(&As_h[r * AST + c * 4])     = h01;
            *reinterpret_cast<uint32_t*>(&As_h[r * AST + c * 4 + 2]) = h23;
            *reinterpret_cast<uint32_t*>(&As_l[r * AST + c * 4])     = l01;
            *reinterpret_cast<uint32_t*>(&As_l[r * AST + c * 4 + 2]) = l23;
        }
#pragma unroll
        for (int i = 0; i < 2; i++) {
            int idx = tid + i * 256;
            int n = idx >> 2, c = idx & 3;
            *reinterpret_cast<uint4*>(&Bs_h[n * AST + c * 8]) =
                *reinterpret_cast<const uint4*>(&g_W1Th[n * IN_F + kt + c * 8]);
            *reinterpret_cast<uint4*>(&Bs_l[n * AST + c * 8]) =
                *reinterpret_cast<const uint4*>(&g_W1Tl[n * IN_F + kt + c * 8]);
        }
        __syncthreads();

#pragma unroll
        for (int ks = 0; ks < 2; ks++) {
            uint32_t ah[2][4], al[2][4], bh[4][2], bl[4][2];
#pragma unroll
            for (int mi = 0; mi < 2; mi++) {
                const uint16_t* pH = &As_h[(wm * 32 + mi * 16 + g) * AST + ks * 16 + tq * 2];
                const uint16_t* pL = &As_l[(wm * 32 + mi * 16 + g) * AST + ks * 16 + tq * 2];
                ah[mi][0] = *reinterpret_cast<const uint32_t*>(pH);
                ah[mi][1] = *reinterpret_cast<const uint32_t*>(pH + 8 * AST);
                ah[mi][2] = *reinterpret_cast<const uint32_t*>(pH + 8);
                ah[mi][3] = *reinterpret_cast<const uint32_t*>(pH + 8 * AST + 8);
                al[mi][0] = *reinterpret_cast<const uint32_t*>(pL);
                al[mi][1] = *reinterpret_cast<const uint32_t*>(pL + 8 * AST);
                al[mi][2] = *reinterpret_cast<const uint32_t*>(pL + 8);
                al[mi][3] = *reinterpret_cast<const uint32_t*>(pL + 8 * AST + 8);
            }
#pragma unroll
            for (int ni = 0; ni < 4; ni++) {
                const uint16_t* pH = &Bs_h[(wn * 32 + ni * 8 + g) * AST + ks * 16 + tq * 2];
                const uint16_t* pL = &Bs_l[(wn * 32 + ni * 8 + g) * AST + ks * 16 + tq * 2];
                bh[ni][0] = *reinterpret_cast<const uint32_t*>(pH);
                bh[ni][1] = *reinterpret_cast<const uint32_t*>(pH + 8);
                bl[ni][0] = *reinterpret_cast<const uint32_t*>(pL);
                bl[ni][1] = *reinterpret_cast<const uint32_t*>(pL + 8);
            }
#pragma unroll
            for (int mi = 0; mi < 2; mi++)
#pragma unroll
                for (int ni = 0; ni < 4; ni++) {
                    mma_bf16(acc[mi][ni], ah[mi], bh[ni]);
                    mma_bf16(acc[mi][ni], ah[mi], bl[ni]);
                    mma_bf16(acc[mi][ni], al[mi], bh[ni]);
                }
        }
        __syncthreads();
    }

#pragma unroll
    for (int mi = 0; mi < 2; mi++)
#pragma unroll
        for (int ni = 0; ni < 4; ni++) {
            int row0 = m0 + wm * 32 + mi * 16 + g;
            int col  = wn * 32 + ni * 8 + tq * 2;
            if (row0 < NN)
                *reinterpret_cast<__half2*>(&g_Y1h[(size_t)row0 * HID_F + col]) =
                    __floats2half2_rn(acc[mi][ni][0], acc[mi][ni][1]);
            if (row0 + 8 < NN)
                *reinterpret_cast<__half2*>(&g_Y1h[(size_t)(row0 + 8) * HID_F + col]) =
                    __floats2half2_rn(acc[mi][ni][2], acc[mi][ni][3]);
        }
}

// ---------------- GEMM2: Y2 = X2 @ W2 (fp16 out) -----------------------------
__global__ void __launch_bounds__(256) gemm2_k() {
    __shared__ uint16_t As_h[64 * AST], As_l[64 * AST];
    __shared__ uint16_t Bs_h[64 * AST], Bs_l[64 * AST];

    const int tid  = threadIdx.x;
    const int lane = tid & 31;
    const int wid  = tid >> 5;
    const int wm   = wid >> 2;
    const int wn   = wid & 3;
    const int g    = lane >> 2;
    const int tq   = lane & 3;
    const int m0   = blockIdx.x * 64;

    float acc[2][2][4];
#pragma unroll
    for (int mi = 0; mi < 2; mi++)
#pragma unroll
        for (int ni = 0; ni < 2; ni++)
#pragma unroll
            for (int r = 0; r < 4; r++) acc[mi][ni][r] = 0.f;

    for (int kt = 0; kt < HID_F; kt += 32) {
        {
            int r = tid >> 2, c = tid & 3;
            int grow = m0 + r;
            uint4 vh = make_uint4(0u, 0u, 0u, 0u), vl = vh;
            if (grow < NN) {
                vh = *reinterpret_cast<const uint4*>(&g_X2h[(size_t)grow * HID_F + kt + c * 8]);
                vl = *reinterpret_cast<const uint4*>(&g_X2l[(size_t)grow * HID_F + kt + c * 8]);
            }
            *reinterpret_cast<uint4*>(&As_h[r * AST + c * 8]) = vh;
            *reinterpret_cast<uint4*>(&As_l[r * AST + c * 8]) = vl;
        }
        {
            int n = tid >> 2, c = tid & 3;
            *reinterpret_cast<uint4*>(&Bs_h[n * AST + c * 8]) =
                *reinterpret_cast<const uint4*>(&g_W2Th[n * HID_F + kt + c * 8]);
            *reinterpret_cast<uint4*>(&Bs_l[n * AST + c * 8]) =
                *reinterpret_cast<const uint4*>(&g_W2Tl[n * HID_F + kt + c * 8]);
        }
        __syncthreads();

#pragma unroll
        for (int ks = 0; ks < 2; ks++) {
            uint32_t ah[2][4], al[2][4], bh[2][2], bl[2][2];
#pragma unroll
            for (int mi = 0; mi < 2; mi++) {
                const uint16_t* pH = &As_h[(wm * 32 + mi * 16 + g) * AST + ks * 16 + tq * 2];
                const uint16_t* pL = &As_l[(wm * 32 + mi * 16 + g) * AST + ks * 16 + tq * 2];
                ah[mi][0] = *reinterpret_cast<const uint32_t*>(pH);
                ah[mi][1] = *reinterpret_cast<const uint32_t*>(pH + 8 * AST);
                ah[mi][2] = *reinterpret_cast<const uint32_t*>(pH + 8);
                ah[mi][3] = *reinterpret_cast<const uint32_t*>(pH + 8 * AST + 8);
                al[mi][0] = *reinterpret_cast<const uint32_t*>(pL);
                al[mi][1] = *reinterpret_cast<const uint32_t*>(pL + 8 * AST);
                al[mi][2] = *reinterpret_cast<const uint32_t*>(pL + 8);
                al[mi][3] = *reinterpret_cast<const uint32_t*>(pL + 8 * AST + 8);
            }
#pragma unroll
            for (int ni = 0; ni < 2; ni++) {
                const uint16_t* pH = &Bs_h[(wn * 16 + ni * 8 + g) * AST + ks * 16 + tq * 2];
                const uint16_t* pL = &Bs_l[(wn * 16 + ni * 8 + g) * AST + ks * 16 + tq * 2];
                bh[ni][0] = *reinterpret_cast<const uint32_t*>(pH);
                bh[ni][1] = *reinterpret_cast<const uint32_t*>(pH + 8);
                bl[ni][0] = *reinterpret_cast<const uint32_t*>(pL);
                bl[ni][1] = *reinterpret_cast<const uint32_t*>(pL + 8);
            }
#pragma unroll
            for (int mi = 0; mi < 2; mi++)
#pragma unroll
                for (int ni = 0; ni < 2; ni++) {
                    mma_bf16(acc[mi][ni], ah[mi], bh[ni]);
                    mma_bf16(acc[mi][ni], ah[mi], bl[ni]);
                    mma_bf16(acc[mi][ni], al[mi], bh[ni]);
                }
        }
        __syncthreads();
    }

#pragma unroll
    for (int mi = 0; mi < 2; mi++)
#pragma unroll
        for (int ni = 0; ni < 2; ni++) {
            int row0 = m0 + wm * 32 + mi * 16 + g;
            int col  = wn * 16 + ni * 8 + tq * 2;
            if (row0 < NN)
                *reinterpret_cast<__half2*>(&g_Y2h[(size_t)row0 * OUT_F + col]) =
                    __floats2half2_rn(acc[mi][ni][0], acc[mi][ni][1]);
            if (row0 + 8 < NN)
                *reinterpret_cast<__half2*>(&g_Y2h[(size_t)(row0 + 8) * OUT_F + col]) =
                    __floats2half2_rn(acc[mi][ni][2], acc[mi][ni][3]);
        }
}

// ---------------- CSR gather, layer 1 (R11 structure + per-edge dout scale) --
__global__ void __launch_bounds__(256) gather1(const float* __restrict__ b1) {
    int node = blockIdx.x * 8 + (threadIdx.x >> 5);
    if (node >= NN) return;
    int lane  = threadIdx.x & 31;
    int start = g_offs[node];
    int cnt   = g_deg_in[node];

    float4 acc = make_float4(0.f, 0.f, 0.f, 0.f);
    for (int j0 = 0; j0 < cnt; j0 += 32) {
        int m  = min(32, cnt - j0);
        int id = (lane < m) ? __ldg(&g_csr_src[start + j0 + lane]) : 0;
        int j  = 0;
        for (; j + 4 <= m; j += 4) {
            int s0 = __shfl_sync(0xffffffffu, id, j);
            int s1 = __shfl_sync(0xffffffffu, id, j + 1);
            int s2 = __shfl_sync(0xffffffffu, id, j + 2);
            int s3 = __shfl_sync(0xffffffffu, id, j + 3);
            float d0 = __ldg(&g_dout_inv[s0]);
            float d1 = __ldg(&g_dout_inv[s1]);
            float d2 = __ldg(&g_dout_inv[s2]);
            float d3 = __ldg(&g_dout_inv[s3]);
            acc_h4s(acc, &g_Y1h[(size_t)s0 * HID_F + lane * 4], d0);
            acc_h4s(acc, &g_Y1h[(size_t)s1 * HID_F + lane * 4], d1);
            acc_h4s(acc, &g_Y1h[(size_t)s2 * HID_F + lane * 4], d2);
            acc_h4s(acc, &g_Y1h[(size_t)s3 * HID_F + lane * 4], d3);
        }
        for (; j < m; j++) {
            int s = __shfl_sync(0xffffffffu, id, j);
            float d = __ldg(&g_dout_inv[s]);
            acc_h4s(acc, &g_Y1h[(size_t)s * HID_F + lane * 4], d);
        }
    }

    float di = g_din_inv[node], dd = g_dout_inv[node];
    float4 b = *reinterpret_cast<const float4*>(&b1[lane * 4]);
    float f0 = fmaxf(acc.x * di + b.x, 0.f) * dd;
    float f1 = fmaxf(acc.y * di + b.y, 0.f) * dd;
    float f2 = fmaxf(acc.z * di + b.z, 0.f) * dd;
    float f3 = fmaxf(acc.w * di + b.w, 0.f) * dd;
    uint32_t h01, l01, h23, l23;
    split2(f0, f1, h01, l01);
    split2(f2, f3, h23, l23);
    size_t o = (size_t)node * HID_F + lane * 4;
    *reinterpret_cast<uint2*>(&g_X2h[o]) = make_uint2(h01, h23);
    *reinterpret_cast<uint2*>(&g_X2l[o]) = make_uint2(l01, l23);
}

// ---------------- CSR gather, layer 2 (R11 structure, fp16 Y2) ---------------
__global__ void __launch_bounds__(256) gather2(float* __restrict__ out,
                                               const float* __restrict__ b2) {
    int node = blockIdx.x * 8 + (threadIdx.x >> 5);
    if (node >= NN) return;
    int lane  = threadIdx.x & 31;
    int start = g_offs[node];
    int cnt   = g_deg_in[node];

    float2 acc = make_float2(0.f, 0.f);
    for (int j0 = 0; j0 < cnt; j0 += 32) {
        int m  = min(32, cnt - j0);
        int id = (lane < m) ? __ldg(&g_csr_src[start + j0 + lane]) : 0;
        int j  = 0;
        for (; j + 4 <= m; j += 4) {
            int s0 = __shfl_sync(0xffffffffu, id, j);
            int s1 = __shfl_sync(0xffffffffu, id, j + 1);
            int s2 = __shfl_sync(0xffffffffu, id, j + 2);
            int s3 = __shfl_sync(0xffffffffu, id, j + 3);
            float2 v0 = __half22float2(*reinterpret_cast<const __half2*>(&g_Y2h[(size_t)s0 * OUT_F + lane * 2]));
            float2 v1 = __half22float2(*reinterpret_cast<const __half2*>(&g_Y2h[(size_t)s1 * OUT_F + lane * 2]));
            float2 v2 = __half22float2(*reinterpret_cast<const __half2*>(&g_Y2h[(size_t)s2 * OUT_F + lane * 2]));
            float2 v3 = __half22float2(*reinterpret_cast<const __half2*>(&g_Y2h[(size_t)s3 * OUT_F + lane * 2]));
            acc.x += v0.x + v1.x + v2.x + v3.x;
            acc.y += v0.y + v1.y + v2.y + v3.y;
        }
        for (; j < m; j++) {
            int s = __shfl_sync(0xffffffffu, id, j);
            float2 v = __half22float2(*reinterpret_cast<const __half2*>(&g_Y2h[(size_t)s * OUT_F + lane * 2]));
            acc.x += v.x; acc.y += v.y;
        }
    }

    float di = g_din_inv[node];
    float2 b = *reinterpret_cast<const float2*>(&b2[lane * 2]);
    acc.x = acc.x * di + b.x;
    acc.y = acc.y * di + b.y;
    *reinterpret_cast<float2*>(&out[(size_t)node * OUT_F + lane * 2]) = acc;
}

// ---------------- launch ----------------------------------------------------
extern "C" void kernel_launch(void* const* d_in, const int* in_sizes, int n_in,
                              void* d_out, int out_size) {
    (void)in_sizes; (void)n_in; (void)out_size;
    const float* features = (const float*)d_in[0];
    const int*   src      = (const int*)  d_in[1];
    const int*   dst      = (const int*)  d_in[2];
    const float* W1       = (const float*)d_in[3];
    const float* b1       = (const float*)d_in[4];
    const float* W2       = (const float*)d_in[5];
    const float* b2       = (const float*)d_in[6];
    float*       out      = (float*)      d_out;

    const int TPB = 256;
    const int SCAN_BLOCKS = (NN + 1023) / 1024;
    const int WTOT = IN_F * HID_F + HID_F * OUT_F;

    // fork: CSR build chain on side stream, GEMM1 (independent) on main stream
    cudaEventRecord(g_ss.ef, 0);
    cudaStreamWaitEvent(g_ss.s, g_ss.ef, 0);

    zero_degs   <<<(NN + TPB - 1) / TPB, TPB, 0, g_ss.s>>>();
    hist_kernel <<<(EE + TPB - 1) / TPB, TPB, 0, g_ss.s>>>(src, dst);
    scan_block_k<<<SCAN_BLOCKS, 1024, 0, g_ss.s>>>();
    scan_top_k  <<<1, 128, 0, g_ss.s>>>(SCAN_BLOCKS);
    scan_add_k  <<<SCAN_BLOCKS, 1024, 0, g_ss.s>>>();
    csr_fill    <<<(EE + TPB - 1) / TPB, TPB, 0, g_ss.s>>>(src, dst);
    cudaEventRecord(g_ss.ej, g_ss.s);

    split_weights<<<(WTOT + TPB - 1) / TPB, TPB>>>(W1, W2);
    gemm1_k<<<(NN + 63) / 64, 256>>>(features);

    // join: gather1 needs CSR + degrees + Y1
    cudaStreamWaitEvent(0, g_ss.ej, 0);

    gather1<<<(NN + 7) / 8, TPB>>>(b1);
    gemm2_k<<<(NN + 63) / 64, 256>>>();
    gather2<<<(NN + 7) / 8, TPB>>>(out, b2);
}